// round 14
// baseline (speedup 1.0000x reference)
#include <cuda_runtime.h>

// SidedDistance: argmin_j ||S1[b,n]-S2[b,j]||^2, B=4, N=M=8192. Output = float32 indices.
//
// Bit-exact contract (validated R5..R13): reproduce reference f32 lowering exactly:
//   cross = fma(z,sz, fma(y,sy, fl(x*sx)))
//   n     = fl(fl(fl(x^2)+fl(y^2))+fl(z^2))
//   d2    = fl(fl(n1 - 2*cross) + n2)
//   argmin: first index achieving the min.
//
// R13 post-mortem: pipe-bound, occupancy-invariant. 3-GPR-pair f32x2 ops cost rt=3
// (RF bank rule), so the mainloop floor is set by fma-pipe cycles. This round: stage
// {-2x,-2y,-2z,n2}. Scaling by -2 is exact and commutes with RN rounding, so
// c2 = fma(az,-2sz, fma(ay,-2sy, fl(ax*-2sx))) == -2*cross BITWISE, and
// d = fl(fl(n1 + c2) + n2) == reference d2 exactly. This swaps an rt-3 fma2 for an
// rt-2 add2: 13 -> 12 fma-pipe cyc / 2 evals.

#define NBATCH   4
#define NQ       8192
#define M        8192
#define THREADS  1024
#define G        8
#define SLOTS    128
#define QB       256                  // queries per block (2 per slot)
#define CPG      (M / G)              // 1024 candidates per group
#define CHUNK    256
#define NCHUNK   (CPG / CHUNK)        // 4
#define BLOCKS_PER_BATCH (NQ / QB)    // 32
#define QPW      (QB / (THREADS / 32))  // 8 queries per warp in rescan

#define DYN_SMEM_BYTES (M * 16)       // 131072: xs|ys|zs|ws

typedef unsigned long long u64;

__device__ __forceinline__ u64 pk2(float lo, float hi) {
    u64 r; asm("mov.b64 %0, {%1, %2};" : "=l"(r) : "f"(lo), "f"(hi)); return r;
}
__device__ __forceinline__ void upk2(u64 v, float& lo, float& hi) {
    asm("mov.b64 {%0, %1}, %2;" : "=f"(lo), "=f"(hi) : "l"(v));
}
__device__ __forceinline__ u64 mul2(u64 a, u64 b) {
    u64 r; asm("mul.rn.f32x2 %0, %1, %2;" : "=l"(r) : "l"(a), "l"(b)); return r;
}
__device__ __forceinline__ u64 add2(u64 a, u64 b) {
    u64 r; asm("add.rn.f32x2 %0, %1, %2;" : "=l"(r) : "l"(a), "l"(b)); return r;
}
__device__ __forceinline__ u64 fma2_(u64 a, u64 b, u64 c) {
    u64 r; asm("fma.rn.f32x2 %0, %1, %2, %3;" : "=l"(r) : "l"(a), "l"(b), "l"(c)); return r;
}

__global__ __launch_bounds__(THREADS, 1)
void SidedDistance_fused(const float* __restrict__ S1,
                         const float* __restrict__ S2,
                         float* __restrict__ out)
{
    extern __shared__ __align__(16) float dyn[];
    float* xs = dyn;                 // [M] : -2x
    float* ys = dyn + M;             // [M] : -2y
    float* zs = dyn + 2 * M;         // [M] : -2z
    float* ws = dyn + 3 * M;         // [M] : n2 (reference rounding, from RAW coords)
    __shared__ float pv[G][QB];
    __shared__ int   pb[G][QB];
    __shared__ int   mb[QB];

    const int b     = blockIdx.x >> 5;
    const int qc    = blockIdx.x & 31;
    const int qbase = qc * QB;
    const int tid   = threadIdx.x;
    const int slot  = tid & (SLOTS - 1);
    const int g     = tid >> 7;               // 0..7
    const int ql0   = 2 * slot;
    const int ql1   = 2 * slot + 1;

    // ---- stage ALL of S2[b]: {-2x,-2y,-2z, n2(raw)} ----
    const float* s2b = S2 + (size_t)b * M * 3;
    for (int j = tid; j < M; j += THREADS) {
        const float* q = s2b + 3 * j;
        float x = q[0], y = q[1], z = q[2];
        xs[j] = __fmul_rn(-2.0f, x);
        ys[j] = __fmul_rn(-2.0f, y);
        zs[j] = __fmul_rn(-2.0f, z);
        ws[j] = __fadd_rn(__fadd_rn(__fmul_rn(x, x), __fmul_rn(y, y)),
                          __fmul_rn(z, z));
    }

    // queries + n1 (reference rounding)
    const float* s1b = S1 + ((size_t)b * NQ + qbase) * 3;
    const float ax0 = s1b[3 * ql0 + 0], ay0 = s1b[3 * ql0 + 1], az0 = s1b[3 * ql0 + 2];
    const float ax1 = s1b[3 * ql1 + 0], ay1 = s1b[3 * ql1 + 1], az1 = s1b[3 * ql1 + 2];
    const float n1_0 = __fadd_rn(__fadd_rn(__fmul_rn(ax0, ax0), __fmul_rn(ay0, ay0)),
                                 __fmul_rn(az0, az0));
    const float n1_1 = __fadd_rn(__fadd_rn(__fmul_rn(ax1, ax1), __fmul_rn(ay1, ay1)),
                                 __fmul_rn(az1, az1));

    const u64 qx0 = pk2(ax0, ax0), qy0 = pk2(ay0, ay0), qz0 = pk2(az0, az0);
    const u64 qx1 = pk2(ax1, ax1), qy1 = pk2(ay1, ay1), qz1 = pk2(az1, az1);
    const u64 N10 = pk2(n1_0, n1_0), N11 = pk2(n1_1, n1_1);

    const float INF = __int_as_float(0x7f800000);

    __syncthreads();

    // ---- pass 1: per-chunk value-only mins over this group's 1024 candidates ----
    // c2 = fma2(qz,Z2, fma2(qy,Y2, mul2(qx,X2))) == -2*cross (exact);
    // d  = add2(add2(N1, c2), W) == fl(fl(n1-2c)+n2) (reference value, bit-exact)
    float cmin0[NCHUNK], cmin1[NCHUNK];
#pragma unroll
    for (int c = 0; c < NCHUNK; ++c) {
        const int off = g * CPG + c * CHUNK;
        float a0e = INF, a0o = INF, a1e = INF, a1o = INF;
#pragma unroll 8
        for (int k = 0; k < CHUNK; k += 4) {
            ulonglong2 X = *reinterpret_cast<const ulonglong2*>(xs + off + k);
            ulonglong2 Y = *reinterpret_cast<const ulonglong2*>(ys + off + k);
            ulonglong2 Z = *reinterpret_cast<const ulonglong2*>(zs + off + k);
            ulonglong2 W = *reinterpret_cast<const ulonglong2*>(ws + off + k);
            float l, h;
            {
                u64 c01 = fma2_(qz0, Z.x, fma2_(qy0, Y.x, mul2(qx0, X.x)));
                u64 c23 = fma2_(qz0, Z.y, fma2_(qy0, Y.y, mul2(qx0, X.y)));
                u64 d01 = add2(add2(N10, c01), W.x);
                u64 d23 = add2(add2(N10, c23), W.y);
                upk2(d01, l, h); a0e = fminf(a0e, l); a0o = fminf(a0o, h);
                upk2(d23, l, h); a0e = fminf(a0e, l); a0o = fminf(a0o, h);
            }
            {
                u64 c01 = fma2_(qz1, Z.x, fma2_(qy1, Y.x, mul2(qx1, X.x)));
                u64 c23 = fma2_(qz1, Z.y, fma2_(qy1, Y.y, mul2(qx1, X.y)));
                u64 d01 = add2(add2(N11, c01), W.x);
                u64 d23 = add2(add2(N11, c23), W.y);
                upk2(d01, l, h); a1e = fminf(a1e, l); a1o = fminf(a1o, h);
                upk2(d23, l, h); a1e = fminf(a1e, l); a1o = fminf(a1o, h);
            }
        }
        cmin0[c] = fminf(a0e, a0o);
        cmin1[c] = fminf(a1e, a1o);
    }

    // winning chunk per query (smallest chunk id on value ties)
    float m0 = cmin0[0], m1 = cmin1[0];
#pragma unroll
    for (int c = 1; c < NCHUNK; ++c) { m0 = fminf(m0, cmin0[c]); m1 = fminf(m1, cmin1[c]); }
    int cc0 = 0, cc1 = 0;
#pragma unroll
    for (int c = NCHUNK - 1; c >= 0; --c) {
        if (cmin0[c] == m0) cc0 = c;
        if (cmin1[c] == m1) cc1 = c;
    }

    pv[g][ql0] = m0;  pb[g][ql0] = g * CPG + cc0 * CHUNK;
    pv[g][ql1] = m1;  pb[g][ql1] = g * CPG + cc1 * CHUNK;
    __syncthreads();

    // merge groups: value, then smaller base on exact ties
    if (tid < QB) {
        float bv = pv[0][tid];
        int   bb = pb[0][tid];
#pragma unroll
        for (int gg = 1; gg < G; ++gg) {
            float v  = pv[gg][tid];
            int   bs = pb[gg][tid];
            if (v < bv || (v == bv && bs < bb)) { bv = v; bb = bs; }
        }
        mb[tid] = bb;
    }
    __syncthreads();

    // ---- fused rescan from transformed smem (same -2-scaled identity, scalar) ----
    const int warp = tid >> 5;
    const int lane = tid & 31;
    for (int i = 0; i < QPW; ++i) {
        const int q    = warp * QPW + i;
        const int base = mb[q];

        const float* s1q = s1b + 3 * q;
        const float ax = s1q[0], ay = s1q[1], az = s1q[2];
        const float n1 = __fadd_rn(__fadd_rn(__fmul_rn(ax, ax), __fmul_rn(ay, ay)),
                                   __fmul_rn(az, az));

        float best = INF;
        int   bj   = base;
#pragma unroll
        for (int r = 0; r < CHUNK / 32; ++r) {
            const int j = base + r * 32 + lane;       // stride-1 across lanes
            float x2 = xs[j], y2 = ys[j], z2 = zs[j], w = ws[j];
            // c2 = -2*cross exactly; d = fl(fl(n1+c2)+n2) = reference d2
            float c2 = __fmaf_rn(az, z2, __fmaf_rn(ay, y2, __fmul_rn(ax, x2)));
            float d  = __fadd_rn(__fadd_rn(n1, c2), w);
            if (d < best) { best = d; bj = j; }       // ascending => first idx per lane
        }
#pragma unroll
        for (int m = 16; m >= 1; m >>= 1) {
            float v2 = __shfl_xor_sync(0xffffffffu, best, m);
            int   j2 = __shfl_xor_sync(0xffffffffu, bj,   m);
            if (v2 < best || (v2 == best && j2 < bj)) { best = v2; bj = j2; }
        }
        if (lane == 0) out[(size_t)b * NQ + qbase + q] = (float)bj;
    }
}

extern "C" void kernel_launch(void* const* d_in, const int* in_sizes, int n_in,
                              void* d_out, int out_size)
{
    const float* S1 = (const float*)d_in[0];
    const float* S2 = (const float*)d_in[1];
    float* out = (float*)d_out;

    cudaFuncSetAttribute(SidedDistance_fused,
                         cudaFuncAttributeMaxDynamicSharedMemorySize, DYN_SMEM_BYTES);

    SidedDistance_fused<<<NBATCH * BLOCKS_PER_BATCH, THREADS, DYN_SMEM_BYTES>>>(S1, S2, out);
}

// round 15
// speedup vs baseline: 1.0264x; 1.0264x over previous
#include <cuda_runtime.h>

// SidedDistance: argmin_j ||S1[b,n]-S2[b,j]||^2, B=4, N=M=8192. Output = float32 indices.
//
// Bit-exact contract (validated R5..R14): reproduce reference f32 lowering exactly:
//   cross = fma(z,sz, fma(y,sy, fl(x*sx)));  n = fl(fl(x^2)+fl(y^2))+fl(z^2) rounded;
//   d2 = fl(fl(n1 - 2*cross) + n2); argmin = first index achieving the min.
//   Staged as {-2x,-2y,-2z,n2}: scaling by -2 is exact & commutes with RN, so
//   d = fl(fl(n1 + c2) + n2) with c2 = fma(az,-2z, fma(ay,-2y, fl(ax*-2x))) is
//   BITWISE equal to the reference d2.
//
// R14 post-mortem: duration invariant (~70us) across occupancy & op-count changes =>
// SM-wide smem crossbar bound: broadcast LDS.128 = 512B through 128B/cyc = 4cyc;
// 32K such per block = 131K cyc = the measured 73us. THIS ROUND: 4 queries per thread
// (G=16 x 64 slots x 4 q/slot) so each candidate load is amortized over 4 queries,
// LDS.64 (2 cands) at 2cyc -> crossbar floor halves to ~36us.

#define NBATCH   4
#define NQ       8192
#define M        8192
#define THREADS  1024
#define G        16
#define SLOTS    64
#define QPS      4                    // queries per slot
#define QB       (SLOTS * QPS)        // 256 queries per block
#define CPG      (M / G)              // 512 candidates per group
#define CHUNK    256
#define NCHUNK   (CPG / CHUNK)        // 2
#define BLOCKS_PER_BATCH (NQ / QB)    // 32
#define QPW      (QB / (THREADS / 32))  // 8 queries per warp in rescan

#define DYN_SMEM_BYTES (M * 16)       // 131072: xs|ys|zs|ws

typedef unsigned long long u64;

__device__ __forceinline__ u64 pk2(float lo, float hi) {
    u64 r; asm("mov.b64 %0, {%1, %2};" : "=l"(r) : "f"(lo), "f"(hi)); return r;
}
__device__ __forceinline__ void upk2(u64 v, float& lo, float& hi) {
    asm("mov.b64 {%0, %1}, %2;" : "=f"(lo), "=f"(hi) : "l"(v));
}
__device__ __forceinline__ u64 mul2(u64 a, u64 b) {
    u64 r; asm("mul.rn.f32x2 %0, %1, %2;" : "=l"(r) : "l"(a), "l"(b)); return r;
}
__device__ __forceinline__ u64 add2(u64 a, u64 b) {
    u64 r; asm("add.rn.f32x2 %0, %1, %2;" : "=l"(r) : "l"(a), "l"(b)); return r;
}
__device__ __forceinline__ u64 fma2_(u64 a, u64 b, u64 c) {
    u64 r; asm("fma.rn.f32x2 %0, %1, %2, %3;" : "=l"(r) : "l"(a), "l"(b), "l"(c)); return r;
}

__global__ __launch_bounds__(THREADS, 1)
void SidedDistance_fused(const float* __restrict__ S1,
                         const float* __restrict__ S2,
                         float* __restrict__ out)
{
    extern __shared__ __align__(16) float dyn[];
    float* xs = dyn;                 // [M] : -2x
    float* ys = dyn + M;             // [M] : -2y
    float* zs = dyn + 2 * M;         // [M] : -2z
    float* ws = dyn + 3 * M;         // [M] : n2 (reference rounding, raw coords)
    __shared__ float pv[G][QB];      // 16 KB
    __shared__ int   pb[G][QB];      // 16 KB
    __shared__ int   mb[QB];

    const int b     = blockIdx.x >> 5;
    const int qc    = blockIdx.x & 31;
    const int qbase = qc * QB;
    const int tid   = threadIdx.x;
    const int slot  = tid & (SLOTS - 1);
    const int g     = tid >> 6;               // 0..15
    const int ql    = QPS * slot;             // first of 4 local queries

    // ---- stage ALL of S2[b]: {-2x,-2y,-2z, n2(raw)} ----
    const float* s2b = S2 + (size_t)b * M * 3;
    for (int j = tid; j < M; j += THREADS) {
        const float* q = s2b + 3 * j;
        float x = q[0], y = q[1], z = q[2];
        xs[j] = __fmul_rn(-2.0f, x);
        ys[j] = __fmul_rn(-2.0f, y);
        zs[j] = __fmul_rn(-2.0f, z);
        ws[j] = __fadd_rn(__fadd_rn(__fmul_rn(x, x), __fmul_rn(y, y)),
                          __fmul_rn(z, z));
    }

    // 4 queries + n1 (reference rounding), packed
    const float* s1b = S1 + ((size_t)b * NQ + qbase) * 3;
    u64 qx[QPS], qy[QPS], qz[QPS], N1[QPS];
#pragma unroll
    for (int i = 0; i < QPS; ++i) {
        const float* p = s1b + 3 * (ql + i);
        float ax = p[0], ay = p[1], az = p[2];
        float n1 = __fadd_rn(__fadd_rn(__fmul_rn(ax, ax), __fmul_rn(ay, ay)),
                             __fmul_rn(az, az));
        qx[i] = pk2(ax, ax); qy[i] = pk2(ay, ay); qz[i] = pk2(az, az);
        N1[i] = pk2(n1, n1);
    }

    const float INF = __int_as_float(0x7f800000);

    __syncthreads();

    // ---- pass 1: per-chunk value-only mins; 2 cands x 4 queries per iteration ----
    float cmin[QPS][NCHUNK];
#pragma unroll
    for (int c = 0; c < NCHUNK; ++c) {
        const int off = g * CPG + c * CHUNK;
        float ae[QPS], ao[QPS];
#pragma unroll
        for (int i = 0; i < QPS; ++i) { ae[i] = INF; ao[i] = INF; }
#pragma unroll 8
        for (int k = 0; k < CHUNK; k += 2) {
            u64 X = *reinterpret_cast<const u64*>(xs + off + k);
            u64 Y = *reinterpret_cast<const u64*>(ys + off + k);
            u64 Z = *reinterpret_cast<const u64*>(zs + off + k);
            u64 W = *reinterpret_cast<const u64*>(ws + off + k);
#pragma unroll
            for (int i = 0; i < QPS; ++i) {
                u64 c01 = fma2_(qz[i], Z, fma2_(qy[i], Y, mul2(qx[i], X)));
                u64 d01 = add2(add2(N1[i], c01), W);
                float l, h;
                upk2(d01, l, h);
                ae[i] = fminf(ae[i], l);
                ao[i] = fminf(ao[i], h);
            }
        }
#pragma unroll
        for (int i = 0; i < QPS; ++i) cmin[i][c] = fminf(ae[i], ao[i]);
    }

    // winning chunk per query (smaller chunk id on value ties) + publish
#pragma unroll
    for (int i = 0; i < QPS; ++i) {
        float m = cmin[i][0];
        int cc = 0;
#pragma unroll
        for (int c = 1; c < NCHUNK; ++c) if (cmin[i][c] < m) { m = cmin[i][c]; cc = c; }
        pv[g][ql + i] = m;
        pb[g][ql + i] = g * CPG + cc * CHUNK;
    }
    __syncthreads();

    // merge groups: value, then smaller base on exact ties
    if (tid < QB) {
        float bv = pv[0][tid];
        int   bb = pb[0][tid];
#pragma unroll
        for (int gg = 1; gg < G; ++gg) {
            float v  = pv[gg][tid];
            int   bs = pb[gg][tid];
            if (v < bv || (v == bv && bs < bb)) { bv = v; bb = bs; }
        }
        mb[tid] = bb;
    }
    __syncthreads();

    // ---- fused rescan from transformed smem (scalar, bit-exact identity) ----
    const int warp = tid >> 5;
    const int lane = tid & 31;
    for (int i = 0; i < QPW; ++i) {
        const int q    = warp * QPW + i;
        const int base = mb[q];

        const float* s1q = s1b + 3 * q;
        const float ax = s1q[0], ay = s1q[1], az = s1q[2];
        const float n1 = __fadd_rn(__fadd_rn(__fmul_rn(ax, ax), __fmul_rn(ay, ay)),
                                   __fmul_rn(az, az));

        float best = INF;
        int   bj   = base;
#pragma unroll
        for (int r = 0; r < CHUNK / 32; ++r) {
            const int j = base + r * 32 + lane;       // stride-1 across lanes
            float x2 = xs[j], y2 = ys[j], z2 = zs[j], w = ws[j];
            float c2 = __fmaf_rn(az, z2, __fmaf_rn(ay, y2, __fmul_rn(ax, x2)));
            float d  = __fadd_rn(__fadd_rn(n1, c2), w);
            if (d < best) { best = d; bj = j; }       // ascending => first idx per lane
        }
#pragma unroll
        for (int m = 16; m >= 1; m >>= 1) {
            float v2 = __shfl_xor_sync(0xffffffffu, best, m);
            int   j2 = __shfl_xor_sync(0xffffffffu, bj,   m);
            if (v2 < best || (v2 == best && j2 < bj)) { best = v2; bj = j2; }
        }
        if (lane == 0) out[(size_t)b * NQ + qbase + q] = (float)bj;
    }
}

extern "C" void kernel_launch(void* const* d_in, const int* in_sizes, int n_in,
                              void* d_out, int out_size)
{
    const float* S1 = (const float*)d_in[0];
    const float* S2 = (const float*)d_in[1];
    float* out = (float*)d_out;

    cudaFuncSetAttribute(SidedDistance_fused,
                         cudaFuncAttributeMaxDynamicSharedMemorySize, DYN_SMEM_BYTES);

    SidedDistance_fused<<<NBATCH * BLOCKS_PER_BATCH, THREADS, DYN_SMEM_BYTES>>>(S1, S2, out);
}

// round 16
// speedup vs baseline: 1.0415x; 1.0146x over previous
#include <cuda_runtime.h>

// SidedDistance: argmin_j ||S1[b,n]-S2[b,j]||^2, B=4, N=M=8192. Output = float32 indices.
//
// Exactness contract (validated R5..R15): final values/indices reproduce the reference
// f32 lowering bit-exactly. NEW structure:
//   pass-1 SCREENING (not exact): vt = fma2(qz,Z, fma2(qy,Y, fma2(qx,X,W))) — 3 packed
//     ops (was 5). vt+n1 differs from the exact d2 by <= 8 roundings x ulp(|mag|<4096)
//     => 2*Delta <= 7.8e-3. EPS=0.01 covers it (coords |x|<=13 holds w.p. 1-1e-38).
//   chunk selection: ALL chunks with screen-min <= best + EPS (bitmask per query).
//   pass-2: exact rescan (reference rounding, staged -2 identity) of every selected
//     chunk; global (value, then smaller index) fold => exact first-argmin.
// Rationale: R12-R15 pinned at ~67us = 5 packed ops x rt3 on the fma pipe. 3 ops => ~41us.

#define NBATCH   4
#define NQ       8192
#define M        8192
#define THREADS  1024
#define G        16
#define SLOTS    64
#define QPS      4                      // queries per slot
#define QB       (SLOTS * QPS)          // 256 queries per block
#define CPG      (M / G)                // 512 candidates per group
#define CHUNK    256
#define NCHUNK   (CPG / CHUNK)          // 2 chunks per group
#define NCH_ALL  (G * NCHUNK)           // 32 chunks per block (whole M)
#define BLOCKS_PER_BATCH (NQ / QB)      // 32
#define QPW      (QB / (THREADS / 32))  // 8 queries per warp in rescan
#define EPS      0.01f

#define DYN_SMEM_BYTES (M * 16)         // 131072: xs|ys|zs|ws

typedef unsigned long long u64;

__device__ __forceinline__ u64 pk2(float lo, float hi) {
    u64 r; asm("mov.b64 %0, {%1, %2};" : "=l"(r) : "f"(lo), "f"(hi)); return r;
}
__device__ __forceinline__ void upk2(u64 v, float& lo, float& hi) {
    asm("mov.b64 {%0, %1}, %2;" : "=f"(lo), "=f"(hi) : "l"(v));
}
__device__ __forceinline__ u64 fma2_(u64 a, u64 b, u64 c) {
    u64 r; asm("fma.rn.f32x2 %0, %1, %2, %3;" : "=l"(r) : "l"(a), "l"(b), "l"(c)); return r;
}

__global__ __launch_bounds__(THREADS, 1)
void SidedDistance_fused(const float* __restrict__ S1,
                         const float* __restrict__ S2,
                         float* __restrict__ out)
{
    extern __shared__ __align__(16) float dyn[];
    float* xs = dyn;                 // [M] : -2x
    float* ys = dyn + M;             // [M] : -2y
    float* zs = dyn + 2 * M;         // [M] : -2z
    float* ws = dyn + 3 * M;         // [M] : n2 (reference rounding, raw coords)
    __shared__ float pv[NCH_ALL][QB];        // 32 KB : screening chunk mins
    __shared__ unsigned mbmask[QB];          // 1 KB  : selected-chunk bitmask

    const int b     = blockIdx.x >> 5;
    const int qc    = blockIdx.x & 31;
    const int qbase = qc * QB;
    const int tid   = threadIdx.x;
    const int slot  = tid & (SLOTS - 1);
    const int g     = tid >> 6;               // 0..15
    const int ql    = QPS * slot;             // first of 4 local queries

    // ---- stage ALL of S2[b]: {-2x,-2y,-2z, n2(raw)} ----
    const float* s2b = S2 + (size_t)b * M * 3;
    for (int j = tid; j < M; j += THREADS) {
        const float* q = s2b + 3 * j;
        float x = q[0], y = q[1], z = q[2];
        xs[j] = __fmul_rn(-2.0f, x);
        ys[j] = __fmul_rn(-2.0f, y);
        zs[j] = __fmul_rn(-2.0f, z);
        ws[j] = __fadd_rn(__fadd_rn(__fmul_rn(x, x), __fmul_rn(y, y)),
                          __fmul_rn(z, z));
    }

    // 4 queries, packed (n1 not needed for screening)
    const float* s1b = S1 + ((size_t)b * NQ + qbase) * 3;
    u64 qx[QPS], qy[QPS], qz[QPS];
#pragma unroll
    for (int i = 0; i < QPS; ++i) {
        const float* p = s1b + 3 * (ql + i);
        qx[i] = pk2(p[0], p[0]); qy[i] = pk2(p[1], p[1]); qz[i] = pk2(p[2], p[2]);
    }

    const float INF = __int_as_float(0x7f800000);

    __syncthreads();

    // ---- pass 1 (screening): per-chunk mins of vt = qz*Z + qy*Y + qx*X + W ----
#pragma unroll
    for (int c = 0; c < NCHUNK; ++c) {
        const int off = g * CPG + c * CHUNK;
        float ae[QPS], ao[QPS];
#pragma unroll
        for (int i = 0; i < QPS; ++i) { ae[i] = INF; ao[i] = INF; }
#pragma unroll 8
        for (int k = 0; k < CHUNK; k += 2) {
            u64 X = *reinterpret_cast<const u64*>(xs + off + k);
            u64 Y = *reinterpret_cast<const u64*>(ys + off + k);
            u64 Z = *reinterpret_cast<const u64*>(zs + off + k);
            u64 W = *reinterpret_cast<const u64*>(ws + off + k);
#pragma unroll
            for (int i = 0; i < QPS; ++i) {
                u64 v = fma2_(qz[i], Z, fma2_(qy[i], Y, fma2_(qx[i], X, W)));
                float l, h;
                upk2(v, l, h);
                ae[i] = fminf(ae[i], l);
                ao[i] = fminf(ao[i], h);
            }
        }
#pragma unroll
        for (int i = 0; i < QPS; ++i)
            pv[g * NCHUNK + c][ql + i] = fminf(ae[i], ao[i]);
    }
    __syncthreads();

    // ---- merge: per query, best screening min + EPS-window chunk bitmask ----
    if (tid < QB) {
        float m = pv[0][tid];
#pragma unroll
        for (int cc = 1; cc < NCH_ALL; ++cc) m = fminf(m, pv[cc][tid]);
        const float lim = m + EPS;
        unsigned mask = 0u;
#pragma unroll
        for (int cc = 0; cc < NCH_ALL; ++cc)
            if (pv[cc][tid] <= lim) mask |= (1u << cc);
        mbmask[tid] = mask;
    }
    __syncthreads();

    // ---- pass 2: EXACT rescan of all selected chunks (warp per 8 queries) ----
    const int warp = tid >> 5;
    const int lane = tid & 31;
    for (int i = 0; i < QPW; ++i) {
        const int q = warp * QPW + i;

        const float* s1q = s1b + 3 * q;
        const float ax = s1q[0], ay = s1q[1], az = s1q[2];
        const float n1 = __fadd_rn(__fadd_rn(__fmul_rn(ax, ax), __fmul_rn(ay, ay)),
                                   __fmul_rn(az, az));

        float best = INF;
        int   bj   = 0x7fffffff;
        unsigned mask = mbmask[q];            // uniform across the warp
        while (mask) {
            const int c32 = __ffs(mask) - 1;  // ascending chunk order
            mask &= mask - 1;
            const int base = c32 * CHUNK;
#pragma unroll
            for (int r = 0; r < CHUNK / 32; ++r) {
                const int j = base + r * 32 + lane;   // stride-1 across lanes
                float x2 = xs[j], y2 = ys[j], z2 = zs[j], w = ws[j];
                // exact reference value: c2 = -2*cross bitwise; d = fl(fl(n1+c2)+n2)
                float c2 = __fmaf_rn(az, z2, __fmaf_rn(ay, y2, __fmul_rn(ax, x2)));
                float d  = __fadd_rn(__fadd_rn(n1, c2), w);
                if (d < best || (d == best && j < bj)) { best = d; bj = j; }
            }
        }
        // warp argmin reduce: value, then smaller index on exact ties
#pragma unroll
        for (int m = 16; m >= 1; m >>= 1) {
            float v2 = __shfl_xor_sync(0xffffffffu, best, m);
            int   j2 = __shfl_xor_sync(0xffffffffu, bj,   m);
            if (v2 < best || (v2 == best && j2 < bj)) { best = v2; bj = j2; }
        }
        if (lane == 0) out[(size_t)b * NQ + qbase + q] = (float)bj;
    }
}

extern "C" void kernel_launch(void* const* d_in, const int* in_sizes, int n_in,
                              void* d_out, int out_size)
{
    const float* S1 = (const float*)d_in[0];
    const float* S2 = (const float*)d_in[1];
    float* out = (float*)d_out;

    cudaFuncSetAttribute(SidedDistance_fused,
                         cudaFuncAttributeMaxDynamicSharedMemorySize, DYN_SMEM_BYTES);

    SidedDistance_fused<<<NBATCH * BLOCKS_PER_BATCH, THREADS, DYN_SMEM_BYTES>>>(S1, S2, out);
}